// round 1
// baseline (speedup 1.0000x reference)
#include <cuda_runtime.h>
#include <cuda_bf16.h>

#define N_NODES 100000
#define IN_F    512
#define HID     128
#define NCLS    2
#define MAX_E   1600000

// ---------------- device scratch (static globals; no runtime allocation) ----
__device__ float g_xw  [(size_t)N_NODES * HID];   // norm_src * (X@W1)
__device__ float g_agg1[(size_t)N_NODES * HID];   // layer1 aggregation -> h (in place)
__device__ float g_zs  [(size_t)N_NODES * NCLS];  // norm_src * (h@W2)
__device__ float g_agg2[(size_t)N_NODES * NCLS];  // layer2 aggregation
__device__ float g_norm_src[N_NODES];             // deg -> rsqrt(max(deg,1))
__device__ float g_norm_dst[N_NODES];
__device__ int   g_src32[MAX_E];
__device__ int   g_dst32[MAX_E];
__device__ int   g_is64;

// ---------------- zero scratch ---------------------------------------------
__global__ void zero_kernel() {
    size_t stride = (size_t)gridDim.x * blockDim.x;
    size_t n4 = (size_t)N_NODES * HID / 4;   // agg1 as float4
    float4 z4 = make_float4(0.f, 0.f, 0.f, 0.f);
    for (size_t i = blockIdx.x * (size_t)blockDim.x + threadIdx.x; i < n4; i += stride)
        reinterpret_cast<float4*>(g_agg1)[i] = z4;
    for (size_t i = blockIdx.x * (size_t)blockDim.x + threadIdx.x; i < N_NODES; i += stride) {
        g_norm_src[i] = 0.f;
        g_norm_dst[i] = 0.f;
        g_agg2[i * 2 + 0] = 0.f;
        g_agg2[i * 2 + 1] = 0.f;
    }
}

// ---------------- index dtype detection + conversion ------------------------
__global__ void detect_kernel(const void* src_raw, int E) {
    // int64 positive values < 2^31: every odd 32-bit word is 0.
    const unsigned int* p = (const unsigned int*)src_raw;
    int n = E < 64 ? E : 64;
    int is64 = 1;
    for (int i = 0; i < n; i++)
        if (p[2 * i + 1] != 0u) is64 = 0;
    g_is64 = is64;
}

__global__ void convert_kernel(const void* src_raw, const void* dst_raw, int E) {
    int i = blockIdx.x * blockDim.x + threadIdx.x;
    if (i >= E) return;
    if (g_is64) {
        g_src32[i] = (int)((const long long*)src_raw)[i];
        g_dst32[i] = (int)((const long long*)dst_raw)[i];
    } else {
        g_src32[i] = ((const int*)src_raw)[i];
        g_dst32[i] = ((const int*)dst_raw)[i];
    }
}

// ---------------- degrees + norms ------------------------------------------
__global__ void degree_kernel(int E) {
    int i = blockIdx.x * blockDim.x + threadIdx.x;
    if (i >= E) return;
    atomicAdd(&g_norm_src[g_src32[i]], 1.0f);
    atomicAdd(&g_norm_dst[g_dst32[i]], 1.0f);
}

__global__ void norm_kernel() {
    int i = blockIdx.x * blockDim.x + threadIdx.x;
    if (i >= N_NODES) return;
    g_norm_src[i] = rsqrtf(fmaxf(g_norm_src[i], 1.0f));
    g_norm_dst[i] = rsqrtf(fmaxf(g_norm_dst[i], 1.0f));
}

// ---------------- GEMM1: g_xw = norm_src[row] * (X @ W1) --------------------
// BM=128, BN=128(=HID), BK=8, 256 threads, 8x8 per thread.
__global__ void __launch_bounds__(256) gemm1_kernel(const float* __restrict__ X,
                                                    const float* __restrict__ W1) {
    __shared__ float As[8][128];
    __shared__ float Bs[8][128];

    const int tid = threadIdx.x;
    const int block_row = blockIdx.x * 128;

    // A tile loader: thread loads one float4 of the 128x8 tile
    const int a_m = tid >> 1;            // 0..127
    const int a_k = (tid & 1) * 4;       // 0 or 4
    // B tile loader: thread loads one float4 of the 8x128 tile
    const int b_k = tid >> 5;            // 0..7
    const int b_n = (tid & 31) * 4;      // 0..124

    const int ty = tid >> 4;             // 0..15
    const int tx = tid & 15;             // 0..15

    float acc[8][8];
#pragma unroll
    for (int i = 0; i < 8; i++)
#pragma unroll
        for (int j = 0; j < 8; j++) acc[i][j] = 0.f;

    for (int kk = 0; kk < IN_F; kk += 8) {
        int gr = block_row + a_m;
        float4 av = make_float4(0.f, 0.f, 0.f, 0.f);
        if (gr < N_NODES)
            av = *(const float4*)(X + (size_t)gr * IN_F + kk + a_k);
        As[a_k + 0][a_m] = av.x;
        As[a_k + 1][a_m] = av.y;
        As[a_k + 2][a_m] = av.z;
        As[a_k + 3][a_m] = av.w;

        float4 bv = *(const float4*)(W1 + (size_t)(kk + b_k) * HID + b_n);
        *(float4*)&Bs[b_k][b_n] = bv;
        __syncthreads();

#pragma unroll
        for (int k = 0; k < 8; k++) {
            float4 ra0 = *(const float4*)&As[k][ty * 8];
            float4 ra1 = *(const float4*)&As[k][ty * 8 + 4];
            float4 rb0 = *(const float4*)&Bs[k][tx * 8];
            float4 rb1 = *(const float4*)&Bs[k][tx * 8 + 4];
            float ra[8] = {ra0.x, ra0.y, ra0.z, ra0.w, ra1.x, ra1.y, ra1.z, ra1.w};
            float rb[8] = {rb0.x, rb0.y, rb0.z, rb0.w, rb1.x, rb1.y, rb1.z, rb1.w};
#pragma unroll
            for (int i = 0; i < 8; i++)
#pragma unroll
                for (int j = 0; j < 8; j++)
                    acc[i][j] = fmaf(ra[i], rb[j], acc[i][j]);
        }
        __syncthreads();
    }

#pragma unroll
    for (int i = 0; i < 8; i++) {
        int row = block_row + ty * 8 + i;
        if (row < N_NODES) {
            float ns = g_norm_src[row];
#pragma unroll
            for (int j = 0; j < 8; j++)
                g_xw[(size_t)row * HID + tx * 8 + j] = acc[i][j] * ns;
        }
    }
}

// ---------------- layer1 edge scatter: warp per edge ------------------------
__global__ void __launch_bounds__(256) edge1_kernel(int E) {
    int gid = blockIdx.x * blockDim.x + threadIdx.x;
    int e = gid >> 5;
    if (e >= E) return;
    int lane = gid & 31;
    int s = g_src32[e];
    int d = g_dst32[e];
    float4 v = *(const float4*)&g_xw[(size_t)s * HID + lane * 4];
    float* dp = &g_agg1[(size_t)d * HID + lane * 4];
    atomicAdd(dp + 0, v.x);
    atomicAdd(dp + 1, v.y);
    atomicAdd(dp + 2, v.z);
    atomicAdd(dp + 3, v.w);
}

// ---------------- h = relu(agg1 * norm_dst + b1), in place ------------------
__global__ void relu_kernel(const float* __restrict__ b1) {
    int idx = blockIdx.x * blockDim.x + threadIdx.x;      // one float4 each
    if (idx >= N_NODES * (HID / 4)) return;
    int row = idx >> 5;                                   // HID/4 = 32 float4 per row
    int c4 = idx & 31;
    float nd = g_norm_dst[row];
    float4 v = reinterpret_cast<float4*>(g_agg1)[idx];
    float4 bb = ((const float4*)b1)[c4];
    v.x = fmaxf(v.x * nd + bb.x, 0.f);
    v.y = fmaxf(v.y * nd + bb.y, 0.f);
    v.z = fmaxf(v.z * nd + bb.z, 0.f);
    v.w = fmaxf(v.w * nd + bb.w, 0.f);
    reinterpret_cast<float4*>(g_agg1)[idx] = v;
}

// ---------------- zs = norm_src * (h @ W2): warp per row --------------------
__global__ void __launch_bounds__(256) lin2_kernel(const float* __restrict__ W2) {
    int gid = blockIdx.x * blockDim.x + threadIdx.x;
    int row = gid >> 5;
    if (row >= N_NODES) return;
    int lane = gid & 31;
    float s0 = 0.f, s1 = 0.f;
#pragma unroll
    for (int t = 0; t < 4; t++) {
        int k = lane + t * 32;
        float h = g_agg1[(size_t)row * HID + k];
        s0 = fmaf(h, __ldg(&W2[k * 2 + 0]), s0);
        s1 = fmaf(h, __ldg(&W2[k * 2 + 1]), s1);
    }
#pragma unroll
    for (int off = 16; off > 0; off >>= 1) {
        s0 += __shfl_down_sync(0xffffffffu, s0, off);
        s1 += __shfl_down_sync(0xffffffffu, s1, off);
    }
    if (lane == 0) {
        float ns = g_norm_src[row];
        g_zs[row * 2 + 0] = s0 * ns;
        g_zs[row * 2 + 1] = s1 * ns;
    }
}

// ---------------- layer2 edge scatter: thread per edge ----------------------
__global__ void edge2_kernel(int E) {
    int e = blockIdx.x * blockDim.x + threadIdx.x;
    if (e >= E) return;
    int s = g_src32[e];
    int d = g_dst32[e];
    float2 v = *(const float2*)&g_zs[s * 2];
    atomicAdd(&g_agg2[d * 2 + 0], v.x);
    atomicAdd(&g_agg2[d * 2 + 1], v.y);
}

// ---------------- softmax((agg2 * norm_dst) + b2) ---------------------------
__global__ void softmax_kernel(const float* __restrict__ b2, float* __restrict__ out) {
    int i = blockIdx.x * blockDim.x + threadIdx.x;
    if (i >= N_NODES) return;
    float nd = g_norm_dst[i];
    float2 a = *(const float2*)&g_agg2[i * 2];
    float z0 = a.x * nd + __ldg(&b2[0]);
    float z1 = a.y * nd + __ldg(&b2[1]);
    float m = fmaxf(z0, z1);
    float e0 = __expf(z0 - m);
    float e1 = __expf(z1 - m);
    float inv = 1.0f / (e0 + e1);
    out[i * 2 + 0] = e0 * inv;
    out[i * 2 + 1] = e1 * inv;
}

// ---------------- host ------------------------------------------------------
extern "C" void kernel_launch(void* const* d_in, const int* in_sizes, int n_in,
                              void* d_out, int out_size) {
    const float* X  = (const float*)d_in[0];
    const float* W1 = (const float*)d_in[1];
    const float* b1 = (const float*)d_in[2];
    const float* W2 = (const float*)d_in[3];
    const float* b2 = (const float*)d_in[4];
    const void*  sp = d_in[5];
    const void*  dp = d_in[6];
    const int E = in_sizes[5];
    float* out = (float*)d_out;

    zero_kernel<<<2048, 256>>>();
    detect_kernel<<<1, 1>>>(sp, E);
    convert_kernel<<<(E + 255) / 256, 256>>>(sp, dp, E);
    degree_kernel<<<(E + 255) / 256, 256>>>(E);
    norm_kernel<<<(N_NODES + 255) / 256, 256>>>();
    gemm1_kernel<<<(N_NODES + 127) / 128, 256>>>(X, W1);
    {
        long long threads = (long long)E * 32;
        edge1_kernel<<<(unsigned)((threads + 255) / 256), 256>>>(E);
    }
    relu_kernel<<<(N_NODES * (HID / 4) + 255) / 256, 256>>>(b1);
    lin2_kernel<<<(N_NODES * 32 + 255) / 256, 256>>>(W2);
    edge2_kernel<<<(E + 255) / 256, 256>>>(E);
    softmax_kernel<<<(N_NODES + 255) / 256, 256>>>(b2, out);
}

// round 2
// speedup vs baseline: 1.6134x; 1.6134x over previous
#include <cuda_runtime.h>
#include <cuda_bf16.h>
#include <cstdint>

#define N_NODES 100000
#define IN_F    512
#define HID     128
#define NCLS    2
#define MAX_E   1600000

// ---------------- device scratch (static globals; no runtime allocation) ----
__device__ float g_xw  [(size_t)N_NODES * HID];   // norm_src * (X@W1)
__device__ float g_agg1[(size_t)N_NODES * HID];   // layer1 aggregation
__device__ float g_zs  [(size_t)N_NODES * NCLS];  // norm_src * (h@W2)
__device__ float g_agg2[(size_t)N_NODES * NCLS];  // layer2 aggregation
__device__ float g_norm_src[N_NODES];
__device__ float g_norm_dst[N_NODES];
__device__ int   g_src32[MAX_E];
__device__ int   g_dst32[MAX_E];
__device__ int   g_is64;

// ---------------- zero scratch ---------------------------------------------
__global__ void zero_kernel() {
    size_t stride = (size_t)gridDim.x * blockDim.x;
    size_t n4 = (size_t)N_NODES * HID / 4;
    float4 z4 = make_float4(0.f, 0.f, 0.f, 0.f);
    for (size_t i = blockIdx.x * (size_t)blockDim.x + threadIdx.x; i < n4; i += stride)
        reinterpret_cast<float4*>(g_agg1)[i] = z4;
    for (size_t i = blockIdx.x * (size_t)blockDim.x + threadIdx.x; i < N_NODES; i += stride) {
        g_norm_src[i] = 0.f;
        g_norm_dst[i] = 0.f;
        g_agg2[i * 2 + 0] = 0.f;
        g_agg2[i * 2 + 1] = 0.f;
    }
}

// ---------------- index dtype detection -------------------------------------
__global__ void detect_kernel(const void* src_raw, int E) {
    const unsigned int* p = (const unsigned int*)src_raw;
    int n = E < 64 ? E : 64;
    int is64 = 1;
    for (int i = 0; i < n; i++)
        if (p[2 * i + 1] != 0u) is64 = 0;
    g_is64 = is64;
}

// convert + degree accumulation fused
__global__ void convert_degree_kernel(const void* src_raw, const void* dst_raw, int E) {
    int i = blockIdx.x * blockDim.x + threadIdx.x;
    if (i >= E) return;
    int s, d;
    if (g_is64) {
        s = (int)((const long long*)src_raw)[i];
        d = (int)((const long long*)dst_raw)[i];
    } else {
        s = ((const int*)src_raw)[i];
        d = ((const int*)dst_raw)[i];
    }
    g_src32[i] = s;
    g_dst32[i] = d;
    atomicAdd(&g_norm_src[s], 1.0f);
    atomicAdd(&g_norm_dst[d], 1.0f);
}

__global__ void norm_kernel() {
    int i = blockIdx.x * blockDim.x + threadIdx.x;
    if (i >= N_NODES) return;
    g_norm_src[i] = rsqrtf(fmaxf(g_norm_src[i], 1.0f));
    g_norm_dst[i] = rsqrtf(fmaxf(g_norm_dst[i], 1.0f));
}

// ---------------- GEMM1 (tensor cores, bf16 2-term split) -------------------
// g_xw = norm_src[row] * (X @ W1)
// CTA tile 128x128xK, BK=16 per iter, 512 threads = 16 warps in 4x4 grid.
// Each warp: 32 rows x 32 cols = 2 m16 tiles x 4 n8 tiles of m16n8k16 bf16 mma.
// Split: x = hi + lo (bf16 each); acc += hi*hi + lo*hi + hi*lo.

__device__ __forceinline__ void mma_bf16(float* c, const uint32_t* a, const uint32_t* b) {
    asm volatile(
        "mma.sync.aligned.m16n8k16.row.col.f32.bf16.bf16.f32 "
        "{%0,%1,%2,%3}, {%4,%5,%6,%7}, {%8,%9}, {%0,%1,%2,%3};\n"
        : "+f"(c[0]), "+f"(c[1]), "+f"(c[2]), "+f"(c[3])
        : "r"(a[0]), "r"(a[1]), "r"(a[2]), "r"(a[3]), "r"(b[0]), "r"(b[1]));
}

__device__ __forceinline__ uint32_t pack_bf16_hi(float x, float y,
                                                 float& lox, float& loy) {
    __nv_bfloat16 hx = __float2bfloat16(x);
    __nv_bfloat16 hy = __float2bfloat16(y);
    lox = x - __bfloat162float(hx);
    loy = y - __bfloat162float(hy);
    __nv_bfloat162 p = __halves2bfloat162(hx, hy);
    return *reinterpret_cast<uint32_t*>(&p);
}

__device__ __forceinline__ uint32_t pack_bf16(float x, float y) {
    __nv_bfloat162 p = __halves2bfloat162(__float2bfloat16(x), __float2bfloat16(y));
    return *reinterpret_cast<uint32_t*>(&p);
}

__global__ void __launch_bounds__(512, 1) gemm1_tc_kernel(const float* __restrict__ X,
                                                          const float* __restrict__ W1) {
    // smem: bf16 pairs stored as uint32, padded rows (9 uint32) to dodge conflicts
    __shared__ uint32_t As_hi[128][9];
    __shared__ uint32_t As_lo[128][9];
    __shared__ uint32_t Bs_hi[128][9];   // [n][kpair]
    __shared__ uint32_t Bs_lo[128][9];

    const int tid = threadIdx.x;
    const int warp = tid >> 5;
    const int lane = tid & 31;
    const int g  = lane >> 2;       // groupID 0..7
    const int tg = lane & 3;        // 0..3
    const int wm = warp >> 2;       // 0..3 -> 32-row slab
    const int wn = warp & 3;        // 0..3 -> 32-col slab
    const int block_row = blockIdx.x * 128;

    float acc[2][4][4];
#pragma unroll
    for (int mt = 0; mt < 2; mt++)
#pragma unroll
        for (int nt = 0; nt < 4; nt++)
#pragma unroll
            for (int r = 0; r < 4; r++) acc[mt][nt][r] = 0.f;

    for (int kk = 0; kk < IN_F; kk += 16) {
        // --- load A tile: 128 rows x 16 k (as 8 kpairs) -----------------
#pragma unroll
        for (int it = 0; it < 2; it++) {
            int idx = tid + it * 512;           // 0..1023
            int row = idx >> 3;
            int kp  = idx & 7;
            int gr  = block_row + row;
            float2 v = make_float2(0.f, 0.f);
            if (gr < N_NODES)
                v = *(const float2*)(X + (size_t)gr * IN_F + kk + kp * 2);
            float lx, ly;
            As_hi[row][kp] = pack_bf16_hi(v.x, v.y, lx, ly);
            As_lo[row][kp] = pack_bf16(lx, ly);
        }
        // --- load B tile: W1[kk..kk+15][0..127] transposed to [n][kpair] -
#pragma unroll
        for (int it = 0; it < 2; it++) {
            int idx = tid + it * 512;
            int n  = idx & 127;
            int kp = idx >> 7;                  // 0..7
            float f0 = W1[(size_t)(kk + 2 * kp) * HID + n];
            float f1 = W1[(size_t)(kk + 2 * kp + 1) * HID + n];
            float lx, ly;
            Bs_hi[n][kp] = pack_bf16_hi(f0, f1, lx, ly);
            Bs_lo[n][kp] = pack_bf16(lx, ly);
        }
        __syncthreads();

        // --- fragments ---------------------------------------------------
        uint32_t Ahi[2][4], Alo[2][4], Bhi[4][2], Blo[4][2];
#pragma unroll
        for (int mt = 0; mt < 2; mt++) {
            int r0 = wm * 32 + mt * 16 + g;
            int r1 = r0 + 8;
            Ahi[mt][0] = As_hi[r0][tg];     Ahi[mt][1] = As_hi[r1][tg];
            Ahi[mt][2] = As_hi[r0][tg + 4]; Ahi[mt][3] = As_hi[r1][tg + 4];
            Alo[mt][0] = As_lo[r0][tg];     Alo[mt][1] = As_lo[r1][tg];
            Alo[mt][2] = As_lo[r0][tg + 4]; Alo[mt][3] = As_lo[r1][tg + 4];
        }
#pragma unroll
        for (int nt = 0; nt < 4; nt++) {
            int c = wn * 32 + nt * 8 + g;
            Bhi[nt][0] = Bs_hi[c][tg]; Bhi[nt][1] = Bs_hi[c][tg + 4];
            Blo[nt][0] = Bs_lo[c][tg]; Blo[nt][1] = Bs_lo[c][tg + 4];
        }

#pragma unroll
        for (int mt = 0; mt < 2; mt++)
#pragma unroll
            for (int nt = 0; nt < 4; nt++) {
                mma_bf16(acc[mt][nt], Ahi[mt], Bhi[nt]);
                mma_bf16(acc[mt][nt], Alo[mt], Bhi[nt]);
                mma_bf16(acc[mt][nt], Ahi[mt], Blo[nt]);
            }
        __syncthreads();
    }

    // --- epilogue: scale by norm_src, store ------------------------------
#pragma unroll
    for (int mt = 0; mt < 2; mt++) {
        int row0 = block_row + wm * 32 + mt * 16 + g;
        int row1 = row0 + 8;
        float ns0 = (row0 < N_NODES) ? g_norm_src[row0] : 0.f;
        float ns1 = (row1 < N_NODES) ? g_norm_src[row1] : 0.f;
#pragma unroll
        for (int nt = 0; nt < 4; nt++) {
            int col = wn * 32 + nt * 8 + 2 * tg;
            if (row0 < N_NODES) {
                float2 v = make_float2(acc[mt][nt][0] * ns0, acc[mt][nt][1] * ns0);
                *(float2*)&g_xw[(size_t)row0 * HID + col] = v;
            }
            if (row1 < N_NODES) {
                float2 v = make_float2(acc[mt][nt][2] * ns1, acc[mt][nt][3] * ns1);
                *(float2*)&g_xw[(size_t)row1 * HID + col] = v;
            }
        }
    }
}

// ---------------- layer1 edge scatter: warp per edge, vector red ------------
__global__ void __launch_bounds__(256) edge1_kernel(int E) {
    int gid = blockIdx.x * blockDim.x + threadIdx.x;
    int e = gid >> 5;
    if (e >= E) return;
    int lane = gid & 31;
    int s = g_src32[e];
    int d = g_dst32[e];
    float4 v = *(const float4*)&g_xw[(size_t)s * HID + lane * 4];
    unsigned long long p =
        (unsigned long long)__cvta_generic_to_global(&g_agg1[(size_t)d * HID + lane * 4]);
    asm volatile("red.global.add.v4.f32 [%0], {%1,%2,%3,%4};"
                 :: "l"(p), "f"(v.x), "f"(v.y), "f"(v.z), "f"(v.w) : "memory");
}

// ---------------- fused: h = relu(agg1*nd + b1); zs = ns * (h @ W2) ---------
__global__ void __launch_bounds__(256) lin2_kernel(const float* __restrict__ b1,
                                                   const float* __restrict__ W2) {
    int gid = blockIdx.x * blockDim.x + threadIdx.x;
    int row = gid >> 5;
    if (row >= N_NODES) return;
    int lane = gid & 31;
    float nd = g_norm_dst[row];
    float s0 = 0.f, s1 = 0.f;
#pragma unroll
    for (int t = 0; t < 4; t++) {
        int k = lane + t * 32;
        float a = g_agg1[(size_t)row * HID + k];
        float h = fmaxf(a * nd + __ldg(&b1[k]), 0.f);
        s0 = fmaf(h, __ldg(&W2[k * 2 + 0]), s0);
        s1 = fmaf(h, __ldg(&W2[k * 2 + 1]), s1);
    }
#pragma unroll
    for (int off = 16; off > 0; off >>= 1) {
        s0 += __shfl_down_sync(0xffffffffu, s0, off);
        s1 += __shfl_down_sync(0xffffffffu, s1, off);
    }
    if (lane == 0) {
        float ns = g_norm_src[row];
        g_zs[row * 2 + 0] = s0 * ns;
        g_zs[row * 2 + 1] = s1 * ns;
    }
}

// ---------------- layer2 edge scatter: thread per edge, vector red ----------
__global__ void edge2_kernel(int E) {
    int e = blockIdx.x * blockDim.x + threadIdx.x;
    if (e >= E) return;
    int s = g_src32[e];
    int d = g_dst32[e];
    float2 v = *(const float2*)&g_zs[s * 2];
    unsigned long long p =
        (unsigned long long)__cvta_generic_to_global(&g_agg2[d * 2]);
    asm volatile("red.global.add.v2.f32 [%0], {%1,%2};"
                 :: "l"(p), "f"(v.x), "f"(v.y) : "memory");
}

// ---------------- softmax((agg2 * norm_dst) + b2) ---------------------------
__global__ void softmax_kernel(const float* __restrict__ b2, float* __restrict__ out) {
    int i = blockIdx.x * blockDim.x + threadIdx.x;
    if (i >= N_NODES) return;
    float nd = g_norm_dst[i];
    float2 a = *(const float2*)&g_agg2[i * 2];
    float z0 = a.x * nd + __ldg(&b2[0]);
    float z1 = a.y * nd + __ldg(&b2[1]);
    float m = fmaxf(z0, z1);
    float e0 = __expf(z0 - m);
    float e1 = __expf(z1 - m);
    float inv = 1.0f / (e0 + e1);
    out[i * 2 + 0] = e0 * inv;
    out[i * 2 + 1] = e1 * inv;
}

// ---------------- host ------------------------------------------------------
extern "C" void kernel_launch(void* const* d_in, const int* in_sizes, int n_in,
                              void* d_out, int out_size) {
    const float* X  = (const float*)d_in[0];
    const float* W1 = (const float*)d_in[1];
    const float* b1 = (const float*)d_in[2];
    const float* W2 = (const float*)d_in[3];
    const float* b2 = (const float*)d_in[4];
    const void*  sp = d_in[5];
    const void*  dp = d_in[6];
    const int E = in_sizes[5];
    float* out = (float*)d_out;

    zero_kernel<<<2048, 256>>>();
    detect_kernel<<<1, 1>>>(sp, E);
    convert_degree_kernel<<<(E + 255) / 256, 256>>>(sp, dp, E);
    norm_kernel<<<(N_NODES + 255) / 256, 256>>>();
    gemm1_tc_kernel<<<(N_NODES + 127) / 128, 512>>>(X, W1);
    {
        long long threads = (long long)E * 32;
        edge1_kernel<<<(unsigned)((threads + 255) / 256), 256>>>(E);
    }
    lin2_kernel<<<(N_NODES * 32 + 255) / 256, 256>>>(b1, W2);
    edge2_kernel<<<(E + 255) / 256, 256>>>(E);
    softmax_kernel<<<(N_NODES + 255) / 256, 256>>>(b2, out);
}

// round 3
// speedup vs baseline: 2.1378x; 1.3250x over previous
#include <cuda_runtime.h>
#include <cuda_bf16.h>
#include <cstdint>

#define N_NODES 100000
#define IN_F    512
#define HID     128
#define NCLS    2
#define MAX_E   1600000
#define SCAN_BLK 1024
#define NUM_SCAN_BLKS ((N_NODES + SCAN_BLK - 1) / SCAN_BLK)   // 98

// ---------------- device scratch (static globals; no runtime allocation) ----
__device__ float g_xw [(size_t)N_NODES * HID];    // norm_src * (X@W1)
__device__ float g_zs [(size_t)N_NODES * NCLS];   // norm_src * (h@W2)
__device__ float g_norm_src[N_NODES];
__device__ float g_norm_dst[N_NODES];
__device__ int   g_src32[MAX_E];
__device__ int   g_dst32[MAX_E];
__device__ int   g_csr_src[MAX_E];                // src ids grouped by dst
__device__ int   g_in_cnt[N_NODES];
__device__ int   g_out_cnt[N_NODES];
__device__ int   g_row_start[N_NODES];            // incl-scan then excl offsets
__device__ int   g_cursor[N_NODES];
__device__ int   g_blk_sums[NUM_SCAN_BLKS];
__device__ int   g_blk_off[NUM_SCAN_BLKS];
__device__ int   g_is64;

// ---------------- zero the histograms ---------------------------------------
__global__ void zero_kernel() {
    int i = blockIdx.x * blockDim.x + threadIdx.x;
    if (i < N_NODES) {
        g_in_cnt[i] = 0;
        g_out_cnt[i] = 0;
    }
}

// ---------------- index dtype detection -------------------------------------
__global__ void detect_kernel(const void* src_raw, int E) {
    const unsigned int* p = (const unsigned int*)src_raw;
    int n = E < 64 ? E : 64;
    int is64 = 1;
    for (int i = 0; i < n; i++)
        if (p[2 * i + 1] != 0u) is64 = 0;
    g_is64 = is64;
}

// ---------------- convert + degree histograms -------------------------------
__global__ void convert_degree_kernel(const void* src_raw, const void* dst_raw, int E) {
    int i = blockIdx.x * blockDim.x + threadIdx.x;
    if (i >= E) return;
    int s, d;
    if (g_is64) {
        s = (int)((const long long*)src_raw)[i];
        d = (int)((const long long*)dst_raw)[i];
    } else {
        s = ((const int*)src_raw)[i];
        d = ((const int*)dst_raw)[i];
    }
    g_src32[i] = s;
    g_dst32[i] = d;
    atomicAdd(&g_out_cnt[s], 1);
    atomicAdd(&g_in_cnt[d], 1);
}

// ---------------- prefix scan over in_cnt (3 phases) -------------------------
__global__ void __launch_bounds__(SCAN_BLK) scanA_kernel() {
    __shared__ int sh[SCAN_BLK];
    int tid = threadIdx.x;
    int i = blockIdx.x * SCAN_BLK + tid;
    int v = (i < N_NODES) ? g_in_cnt[i] : 0;
    sh[tid] = v;
    __syncthreads();
#pragma unroll
    for (int off = 1; off < SCAN_BLK; off <<= 1) {
        int t = (tid >= off) ? sh[tid - off] : 0;
        __syncthreads();
        sh[tid] += t;
        __syncthreads();
    }
    if (i < N_NODES) g_row_start[i] = sh[tid];        // inclusive
    if (tid == SCAN_BLK - 1) g_blk_sums[blockIdx.x] = sh[tid];
}

__global__ void scanB_kernel() {
    __shared__ int sh[128];
    int tid = threadIdx.x;
    int v = (tid < NUM_SCAN_BLKS) ? g_blk_sums[tid] : 0;
    sh[tid] = v;
    __syncthreads();
#pragma unroll
    for (int off = 1; off < 128; off <<= 1) {
        int t = (tid >= off) ? sh[tid - off] : 0;
        __syncthreads();
        sh[tid] += t;
        __syncthreads();
    }
    if (tid < NUM_SCAN_BLKS) g_blk_off[tid] = sh[tid] - v;   // exclusive
}

__global__ void scanC_kernel() {
    int i = blockIdx.x * blockDim.x + threadIdx.x;
    if (i >= N_NODES) return;
    int excl = g_row_start[i] - g_in_cnt[i] + g_blk_off[i >> 10];
    g_row_start[i] = excl;
    g_cursor[i] = excl;
}

// ---------------- scatter edges into CSR (grouped by dst) --------------------
__global__ void scatter_kernel(int E) {
    int e = blockIdx.x * blockDim.x + threadIdx.x;
    if (e >= E) return;
    int d = g_dst32[e];
    int pos = atomicAdd(&g_cursor[d], 1);
    g_csr_src[pos] = g_src32[e];
}

// ---------------- norms ------------------------------------------------------
__global__ void norm_kernel() {
    int i = blockIdx.x * blockDim.x + threadIdx.x;
    if (i >= N_NODES) return;
    g_norm_src[i] = rsqrtf(fmaxf((float)g_out_cnt[i], 1.0f));
    g_norm_dst[i] = rsqrtf(fmaxf((float)g_in_cnt[i], 1.0f));
}

// ---------------- GEMM1 (tensor cores, bf16 2-term split) -------------------
__device__ __forceinline__ void mma_bf16(float* c, const uint32_t* a, const uint32_t* b) {
    asm volatile(
        "mma.sync.aligned.m16n8k16.row.col.f32.bf16.bf16.f32 "
        "{%0,%1,%2,%3}, {%4,%5,%6,%7}, {%8,%9}, {%0,%1,%2,%3};\n"
        : "+f"(c[0]), "+f"(c[1]), "+f"(c[2]), "+f"(c[3])
        : "r"(a[0]), "r"(a[1]), "r"(a[2]), "r"(a[3]), "r"(b[0]), "r"(b[1]));
}

__device__ __forceinline__ uint32_t pack_bf16_hi(float x, float y,
                                                 float& lox, float& loy) {
    __nv_bfloat16 hx = __float2bfloat16(x);
    __nv_bfloat16 hy = __float2bfloat16(y);
    lox = x - __bfloat162float(hx);
    loy = y - __bfloat162float(hy);
    __nv_bfloat162 p = __halves2bfloat162(hx, hy);
    return *reinterpret_cast<uint32_t*>(&p);
}

__device__ __forceinline__ uint32_t pack_bf16(float x, float y) {
    __nv_bfloat162 p = __halves2bfloat162(__float2bfloat16(x), __float2bfloat16(y));
    return *reinterpret_cast<uint32_t*>(&p);
}

__global__ void __launch_bounds__(512, 1) gemm1_tc_kernel(const float* __restrict__ X,
                                                          const float* __restrict__ W1) {
    __shared__ uint32_t As_hi[128][9];
    __shared__ uint32_t As_lo[128][9];
    __shared__ uint32_t Bs_hi[128][9];
    __shared__ uint32_t Bs_lo[128][9];

    const int tid = threadIdx.x;
    const int warp = tid >> 5;
    const int lane = tid & 31;
    const int g  = lane >> 2;
    const int tg = lane & 3;
    const int wm = warp >> 2;
    const int wn = warp & 3;
    const int block_row = blockIdx.x * 128;

    float acc[2][4][4];
#pragma unroll
    for (int mt = 0; mt < 2; mt++)
#pragma unroll
        for (int nt = 0; nt < 4; nt++)
#pragma unroll
            for (int r = 0; r < 4; r++) acc[mt][nt][r] = 0.f;

    for (int kk = 0; kk < IN_F; kk += 16) {
#pragma unroll
        for (int it = 0; it < 2; it++) {
            int idx = tid + it * 512;
            int row = idx >> 3;
            int kp  = idx & 7;
            int gr  = block_row + row;
            float2 v = make_float2(0.f, 0.f);
            if (gr < N_NODES)
                v = *(const float2*)(X + (size_t)gr * IN_F + kk + kp * 2);
            float lx, ly;
            As_hi[row][kp] = pack_bf16_hi(v.x, v.y, lx, ly);
            As_lo[row][kp] = pack_bf16(lx, ly);
        }
#pragma unroll
        for (int it = 0; it < 2; it++) {
            int idx = tid + it * 512;
            int n  = idx & 127;
            int kp = idx >> 7;
            float f0 = W1[(size_t)(kk + 2 * kp) * HID + n];
            float f1 = W1[(size_t)(kk + 2 * kp + 1) * HID + n];
            float lx, ly;
            Bs_hi[n][kp] = pack_bf16_hi(f0, f1, lx, ly);
            Bs_lo[n][kp] = pack_bf16(lx, ly);
        }
        __syncthreads();

        uint32_t Ahi[2][4], Alo[2][4], Bhi[4][2], Blo[4][2];
#pragma unroll
        for (int mt = 0; mt < 2; mt++) {
            int r0 = wm * 32 + mt * 16 + g;
            int r1 = r0 + 8;
            Ahi[mt][0] = As_hi[r0][tg];     Ahi[mt][1] = As_hi[r1][tg];
            Ahi[mt][2] = As_hi[r0][tg + 4]; Ahi[mt][3] = As_hi[r1][tg + 4];
            Alo[mt][0] = As_lo[r0][tg];     Alo[mt][1] = As_lo[r1][tg];
            Alo[mt][2] = As_lo[r0][tg + 4]; Alo[mt][3] = As_lo[r1][tg + 4];
        }
#pragma unroll
        for (int nt = 0; nt < 4; nt++) {
            int c = wn * 32 + nt * 8 + g;
            Bhi[nt][0] = Bs_hi[c][tg]; Bhi[nt][1] = Bs_hi[c][tg + 4];
            Blo[nt][0] = Bs_lo[c][tg]; Blo[nt][1] = Bs_lo[c][tg + 4];
        }

#pragma unroll
        for (int mt = 0; mt < 2; mt++)
#pragma unroll
            for (int nt = 0; nt < 4; nt++) {
                mma_bf16(acc[mt][nt], Ahi[mt], Bhi[nt]);
                mma_bf16(acc[mt][nt], Alo[mt], Bhi[nt]);
                mma_bf16(acc[mt][nt], Ahi[mt], Blo[nt]);
            }
        __syncthreads();
    }

#pragma unroll
    for (int mt = 0; mt < 2; mt++) {
        int row0 = block_row + wm * 32 + mt * 16 + g;
        int row1 = row0 + 8;
        float ns0 = (row0 < N_NODES) ? g_norm_src[row0] : 0.f;
        float ns1 = (row1 < N_NODES) ? g_norm_src[row1] : 0.f;
#pragma unroll
        for (int nt = 0; nt < 4; nt++) {
            int col = wn * 32 + nt * 8 + 2 * tg;
            if (row0 < N_NODES) {
                float2 v = make_float2(acc[mt][nt][0] * ns0, acc[mt][nt][1] * ns0);
                *(float2*)&g_xw[(size_t)row0 * HID + col] = v;
            }
            if (row1 < N_NODES) {
                float2 v = make_float2(acc[mt][nt][2] * ns1, acc[mt][nt][3] * ns1);
                *(float2*)&g_xw[(size_t)row1 * HID + col] = v;
            }
        }
    }
}

// ---------------- fused layer1: CSR segmented sum + relu + lin2 --------------
// warp per dst node. acc = sum_{e in seg} g_xw[src[e]]; h = relu(acc*nd + b1);
// zs = ns * (h @ W2).
__global__ void __launch_bounds__(256) agg1_fused_kernel(const float* __restrict__ b1,
                                                         const float* __restrict__ W2) {
    __shared__ float sW2[HID * 2];
    __shared__ float sb1[HID];
    for (int i = threadIdx.x; i < HID * 2; i += 256) sW2[i] = W2[i];
    for (int i = threadIdx.x; i < HID; i += 256) sb1[i] = b1[i];
    __syncthreads();

    int gid = blockIdx.x * blockDim.x + threadIdx.x;
    int row = gid >> 5;
    if (row >= N_NODES) return;
    int lane = gid & 31;

    int start = g_row_start[row];
    int cnt   = g_in_cnt[row];
    int end   = start + cnt;

    float4 acc = make_float4(0.f, 0.f, 0.f, 0.f);
    int e = start;
    // unroll by 2 for MLP
    for (; e + 1 < end; e += 2) {
        int s0 = g_csr_src[e];
        int s1 = g_csr_src[e + 1];
        float4 v0 = *(const float4*)&g_xw[(size_t)s0 * HID + lane * 4];
        float4 v1 = *(const float4*)&g_xw[(size_t)s1 * HID + lane * 4];
        acc.x += v0.x + v1.x;
        acc.y += v0.y + v1.y;
        acc.z += v0.z + v1.z;
        acc.w += v0.w + v1.w;
    }
    if (e < end) {
        int s0 = g_csr_src[e];
        float4 v0 = *(const float4*)&g_xw[(size_t)s0 * HID + lane * 4];
        acc.x += v0.x; acc.y += v0.y; acc.z += v0.z; acc.w += v0.w;
    }

    float nd = g_norm_dst[row];
    int k0 = lane * 4;
    float h0 = fmaxf(acc.x * nd + sb1[k0 + 0], 0.f);
    float h1 = fmaxf(acc.y * nd + sb1[k0 + 1], 0.f);
    float h2 = fmaxf(acc.z * nd + sb1[k0 + 2], 0.f);
    float h3 = fmaxf(acc.w * nd + sb1[k0 + 3], 0.f);

    float s0 = h0 * sW2[(k0 + 0) * 2] + h1 * sW2[(k0 + 1) * 2]
             + h2 * sW2[(k0 + 2) * 2] + h3 * sW2[(k0 + 3) * 2];
    float s1 = h0 * sW2[(k0 + 0) * 2 + 1] + h1 * sW2[(k0 + 1) * 2 + 1]
             + h2 * sW2[(k0 + 2) * 2 + 1] + h3 * sW2[(k0 + 3) * 2 + 1];
#pragma unroll
    for (int off = 16; off > 0; off >>= 1) {
        s0 += __shfl_down_sync(0xffffffffu, s0, off);
        s1 += __shfl_down_sync(0xffffffffu, s1, off);
    }
    if (lane == 0) {
        float ns = g_norm_src[row];
        g_zs[row * 2 + 0] = s0 * ns;
        g_zs[row * 2 + 1] = s1 * ns;
    }
}

// ---------------- fused layer2: CSR segmented sum + softmax ------------------
// thread per dst node.
__global__ void agg2_fused_kernel(const float* __restrict__ b2, float* __restrict__ out) {
    int i = blockIdx.x * blockDim.x + threadIdx.x;
    if (i >= N_NODES) return;
    int start = g_row_start[i];
    int end = start + g_in_cnt[i];
    float a0 = 0.f, a1 = 0.f;
    for (int e = start; e < end; e++) {
        int s = g_csr_src[e];
        float2 v = *(const float2*)&g_zs[s * 2];
        a0 += v.x;
        a1 += v.y;
    }
    float nd = g_norm_dst[i];
    float z0 = a0 * nd + __ldg(&b2[0]);
    float z1 = a1 * nd + __ldg(&b2[1]);
    float m = fmaxf(z0, z1);
    float e0 = __expf(z0 - m);
    float e1 = __expf(z1 - m);
    float inv = 1.0f / (e0 + e1);
    out[i * 2 + 0] = e0 * inv;
    out[i * 2 + 1] = e1 * inv;
}

// ---------------- host ------------------------------------------------------
extern "C" void kernel_launch(void* const* d_in, const int* in_sizes, int n_in,
                              void* d_out, int out_size) {
    const float* X  = (const float*)d_in[0];
    const float* W1 = (const float*)d_in[1];
    const float* b1 = (const float*)d_in[2];
    const float* W2 = (const float*)d_in[3];
    const float* b2 = (const float*)d_in[4];
    const void*  sp = d_in[5];
    const void*  dp = d_in[6];
    const int E = in_sizes[5];
    float* out = (float*)d_out;

    zero_kernel<<<(N_NODES + 255) / 256, 256>>>();
    detect_kernel<<<1, 1>>>(sp, E);
    convert_degree_kernel<<<(E + 255) / 256, 256>>>(sp, dp, E);
    scanA_kernel<<<NUM_SCAN_BLKS, SCAN_BLK>>>();
    scanB_kernel<<<1, 128>>>();
    scanC_kernel<<<(N_NODES + 255) / 256, 256>>>();
    scatter_kernel<<<(E + 255) / 256, 256>>>(E);
    norm_kernel<<<(N_NODES + 255) / 256, 256>>>();
    gemm1_tc_kernel<<<(N_NODES + 127) / 128, 512>>>(X, W1);
    {
        long long threads = (long long)N_NODES * 32;
        agg1_fused_kernel<<<(unsigned)((threads + 255) / 256), 256>>>(b1, W2);
    }
    agg2_fused_kernel<<<(N_NODES + 255) / 256, 256>>>(b2, out);
}

// round 4
// speedup vs baseline: 2.5797x; 1.2067x over previous
#include <cuda_runtime.h>
#include <cuda_bf16.h>
#include <cstdint>

#define N_NODES 100000
#define IN_F    512
#define HID     128
#define NCLS    2
#define MAX_E   1600000
#define SCAN_BLK 1024
#define NUM_SCAN_BLKS ((N_NODES + SCAN_BLK - 1) / SCAN_BLK)   // 98

// ---------------- device scratch (static globals; no runtime allocation) ----
__device__ float g_xw [(size_t)N_NODES * HID];    // norm_src * (X@W1)
__device__ float g_zs [(size_t)N_NODES * NCLS];   // norm_src * (h@W2)
__device__ float g_norm_src[N_NODES];
__device__ float g_norm_dst[N_NODES];
__device__ int   g_src32[MAX_E];
__device__ int   g_dst32[MAX_E];
__device__ int   g_csr_src[MAX_E];                // src ids grouped by dst
__device__ int   g_in_cnt[N_NODES];
__device__ int   g_out_cnt[N_NODES];
__device__ int   g_row_start[N_NODES];            // incl-scan then excl offsets
__device__ int   g_cursor[N_NODES];
__device__ int   g_blk_sums[NUM_SCAN_BLKS];
__device__ int   g_blk_off[NUM_SCAN_BLKS];
__device__ int   g_is64;

// ---------------- zero the histograms ---------------------------------------
__global__ void zero_kernel() {
    int i = blockIdx.x * blockDim.x + threadIdx.x;
    if (i < N_NODES) {
        g_in_cnt[i] = 0;
        g_out_cnt[i] = 0;
    }
}

// ---------------- index dtype detection -------------------------------------
__global__ void detect_kernel(const void* src_raw, int E) {
    const unsigned int* p = (const unsigned int*)src_raw;
    int n = E < 64 ? E : 64;
    int is64 = 1;
    for (int i = 0; i < n; i++)
        if (p[2 * i + 1] != 0u) is64 = 0;
    g_is64 = is64;
}

// ---------------- convert + degree histograms -------------------------------
__global__ void convert_degree_kernel(const void* src_raw, const void* dst_raw, int E) {
    int i = blockIdx.x * blockDim.x + threadIdx.x;
    if (i >= E) return;
    int s, d;
    if (g_is64) {
        s = (int)((const long long*)src_raw)[i];
        d = (int)((const long long*)dst_raw)[i];
    } else {
        s = ((const int*)src_raw)[i];
        d = ((const int*)dst_raw)[i];
    }
    g_src32[i] = s;
    g_dst32[i] = d;
    atomicAdd(&g_out_cnt[s], 1);
    atomicAdd(&g_in_cnt[d], 1);
}

// ---------------- prefix scan over in_cnt (3 phases) -------------------------
__global__ void __launch_bounds__(SCAN_BLK) scanA_kernel() {
    __shared__ int sh[SCAN_BLK];
    int tid = threadIdx.x;
    int i = blockIdx.x * SCAN_BLK + tid;
    int v = (i < N_NODES) ? g_in_cnt[i] : 0;
    sh[tid] = v;
    __syncthreads();
#pragma unroll
    for (int off = 1; off < SCAN_BLK; off <<= 1) {
        int t = (tid >= off) ? sh[tid - off] : 0;
        __syncthreads();
        sh[tid] += t;
        __syncthreads();
    }
    if (i < N_NODES) g_row_start[i] = sh[tid];        // inclusive
    if (tid == SCAN_BLK - 1) g_blk_sums[blockIdx.x] = sh[tid];
}

__global__ void scanB_kernel() {
    __shared__ int sh[128];
    int tid = threadIdx.x;
    int v = (tid < NUM_SCAN_BLKS) ? g_blk_sums[tid] : 0;
    sh[tid] = v;
    __syncthreads();
#pragma unroll
    for (int off = 1; off < 128; off <<= 1) {
        int t = (tid >= off) ? sh[tid - off] : 0;
        __syncthreads();
        sh[tid] += t;
        __syncthreads();
    }
    if (tid < NUM_SCAN_BLKS) g_blk_off[tid] = sh[tid] - v;   // exclusive
}

// scanC + norms fused
__global__ void scanC_kernel() {
    int i = blockIdx.x * blockDim.x + threadIdx.x;
    if (i >= N_NODES) return;
    int ic = g_in_cnt[i];
    int excl = g_row_start[i] - ic + g_blk_off[i >> 10];
    g_row_start[i] = excl;
    g_cursor[i] = excl;
    g_norm_src[i] = rsqrtf(fmaxf((float)g_out_cnt[i], 1.0f));
    g_norm_dst[i] = rsqrtf(fmaxf((float)ic, 1.0f));
}

// ---------------- scatter edges into CSR (grouped by dst) --------------------
__global__ void scatter_kernel(int E) {
    int e = blockIdx.x * blockDim.x + threadIdx.x;
    if (e >= E) return;
    int d = g_dst32[e];
    int pos = atomicAdd(&g_cursor[d], 1);
    g_csr_src[pos] = g_src32[e];
}

// ---------------- GEMM1 (tensor cores, bf16 2-term split, reg pipeline) -----
__device__ __forceinline__ void mma_bf16(float* c, const uint32_t* a, const uint32_t* b) {
    asm volatile(
        "mma.sync.aligned.m16n8k16.row.col.f32.bf16.bf16.f32 "
        "{%0,%1,%2,%3}, {%4,%5,%6,%7}, {%8,%9}, {%0,%1,%2,%3};\n"
        : "+f"(c[0]), "+f"(c[1]), "+f"(c[2]), "+f"(c[3])
        : "r"(a[0]), "r"(a[1]), "r"(a[2]), "r"(a[3]), "r"(b[0]), "r"(b[1]));
}

__device__ __forceinline__ uint32_t pack_bf16_hi(float x, float y,
                                                 float& lox, float& loy) {
    __nv_bfloat16 hx = __float2bfloat16(x);
    __nv_bfloat16 hy = __float2bfloat16(y);
    lox = x - __bfloat162float(hx);
    loy = y - __bfloat162float(hy);
    __nv_bfloat162 p = __halves2bfloat162(hx, hy);
    return *reinterpret_cast<uint32_t*>(&p);
}

__device__ __forceinline__ uint32_t pack_bf16(float x, float y) {
    __nv_bfloat162 p = __halves2bfloat162(__float2bfloat16(x), __float2bfloat16(y));
    return *reinterpret_cast<uint32_t*>(&p);
}

__global__ void __launch_bounds__(512, 1) gemm1_tc_kernel(const float* __restrict__ X,
                                                          const float* __restrict__ W1) {
    __shared__ uint32_t As_hi[128][9];
    __shared__ uint32_t As_lo[128][9];
    __shared__ uint32_t Bs_hi[128][9];
    __shared__ uint32_t Bs_lo[128][9];

    const int tid = threadIdx.x;
    const int warp = tid >> 5;
    const int lane = tid & 31;
    const int g  = lane >> 2;
    const int tg = lane & 3;
    const int wm = warp >> 2;
    const int wn = warp & 3;
    const int block_row = blockIdx.x * 128;

    // loader coordinates (2 A-pairs, 2 B-pairs per thread per tile)
    int a_row[2], a_kp[2], b_n[2], b_kp[2];
#pragma unroll
    for (int it = 0; it < 2; it++) {
        int idx = tid + it * 512;
        a_row[it] = idx >> 3;
        a_kp[it]  = idx & 7;
        b_n[it]   = idx & 127;
        b_kp[it]  = idx >> 7;
    }

    float acc[2][4][4];
#pragma unroll
    for (int mt = 0; mt < 2; mt++)
#pragma unroll
        for (int nt = 0; nt < 4; nt++)
#pragma unroll
            for (int r = 0; r < 4; r++) acc[mt][nt][r] = 0.f;

    // prefetch registers
    float2 pa[2];
    float  pb0[2], pb1[2];

    auto load_tile = [&](int kk) {
#pragma unroll
        for (int it = 0; it < 2; it++) {
            int gr = block_row + a_row[it];
            float2 v = make_float2(0.f, 0.f);
            if (gr < N_NODES)
                v = *(const float2*)(X + (size_t)gr * IN_F + kk + a_kp[it] * 2);
            pa[it] = v;
            pb0[it] = W1[(size_t)(kk + 2 * b_kp[it]) * HID + b_n[it]];
            pb1[it] = W1[(size_t)(kk + 2 * b_kp[it] + 1) * HID + b_n[it]];
        }
    };

    auto store_tile = [&]() {
#pragma unroll
        for (int it = 0; it < 2; it++) {
            float lx, ly;
            As_hi[a_row[it]][a_kp[it]] = pack_bf16_hi(pa[it].x, pa[it].y, lx, ly);
            As_lo[a_row[it]][a_kp[it]] = pack_bf16(lx, ly);
            float blx, bly;
            Bs_hi[b_n[it]][b_kp[it]] = pack_bf16_hi(pb0[it], pb1[it], blx, bly);
            Bs_lo[b_n[it]][b_kp[it]] = pack_bf16(blx, bly);
        }
    };

    load_tile(0);

    for (int kk = 0; kk < IN_F; kk += 16) {
        store_tile();
        __syncthreads();

        // issue next tile's global loads early (latency hidden behind MMAs)
        if (kk + 16 < IN_F) load_tile(kk + 16);

        uint32_t Ahi[2][4], Alo[2][4], Bhi[4][2], Blo[4][2];
#pragma unroll
        for (int mt = 0; mt < 2; mt++) {
            int r0 = wm * 32 + mt * 16 + g;
            int r1 = r0 + 8;
            Ahi[mt][0] = As_hi[r0][tg];     Ahi[mt][1] = As_hi[r1][tg];
            Ahi[mt][2] = As_hi[r0][tg + 4]; Ahi[mt][3] = As_hi[r1][tg + 4];
            Alo[mt][0] = As_lo[r0][tg];     Alo[mt][1] = As_lo[r1][tg];
            Alo[mt][2] = As_lo[r0][tg + 4]; Alo[mt][3] = As_lo[r1][tg + 4];
        }
#pragma unroll
        for (int nt = 0; nt < 4; nt++) {
            int c = wn * 32 + nt * 8 + g;
            Bhi[nt][0] = Bs_hi[c][tg]; Bhi[nt][1] = Bs_hi[c][tg + 4];
            Blo[nt][0] = Bs_lo[c][tg]; Blo[nt][1] = Bs_lo[c][tg + 4];
        }

#pragma unroll
        for (int mt = 0; mt < 2; mt++)
#pragma unroll
            for (int nt = 0; nt < 4; nt++) {
                mma_bf16(acc[mt][nt], Ahi[mt], Bhi[nt]);
                mma_bf16(acc[mt][nt], Alo[mt], Bhi[nt]);
                mma_bf16(acc[mt][nt], Ahi[mt], Blo[nt]);
            }
        __syncthreads();
    }

#pragma unroll
    for (int mt = 0; mt < 2; mt++) {
        int row0 = block_row + wm * 32 + mt * 16 + g;
        int row1 = row0 + 8;
        float ns0 = (row0 < N_NODES) ? g_norm_src[row0] : 0.f;
        float ns1 = (row1 < N_NODES) ? g_norm_src[row1] : 0.f;
#pragma unroll
        for (int nt = 0; nt < 4; nt++) {
            int col = wn * 32 + nt * 8 + 2 * tg;
            if (row0 < N_NODES) {
                float2 v = make_float2(acc[mt][nt][0] * ns0, acc[mt][nt][1] * ns0);
                *(float2*)&g_xw[(size_t)row0 * HID + col] = v;
            }
            if (row1 < N_NODES) {
                float2 v = make_float2(acc[mt][nt][2] * ns1, acc[mt][nt][3] * ns1);
                *(float2*)&g_xw[(size_t)row1 * HID + col] = v;
            }
        }
    }
}

// ---------------- fused layer1: CSR segmented sum + relu + lin2 --------------
// warp per dst node; unroll-4 gather for MLP.
__global__ void __launch_bounds__(256) agg1_fused_kernel(const float* __restrict__ b1,
                                                         const float* __restrict__ W2) {
    __shared__ float sW2[HID * 2];
    __shared__ float sb1[HID];
    for (int i = threadIdx.x; i < HID * 2; i += 256) sW2[i] = W2[i];
    for (int i = threadIdx.x; i < HID; i += 256) sb1[i] = b1[i];
    __syncthreads();

    int gid = blockIdx.x * blockDim.x + threadIdx.x;
    int row = gid >> 5;
    if (row >= N_NODES) return;
    int lane = gid & 31;

    int start = g_row_start[row];
    int cnt   = g_in_cnt[row];
    int end   = start + cnt;

    float4 acc = make_float4(0.f, 0.f, 0.f, 0.f);
    int e = start;
    for (; e + 3 < end; e += 4) {
        int s0 = __ldg(&g_csr_src[e + 0]);
        int s1 = __ldg(&g_csr_src[e + 1]);
        int s2 = __ldg(&g_csr_src[e + 2]);
        int s3 = __ldg(&g_csr_src[e + 3]);
        float4 v0 = *(const float4*)&g_xw[(size_t)s0 * HID + lane * 4];
        float4 v1 = *(const float4*)&g_xw[(size_t)s1 * HID + lane * 4];
        float4 v2 = *(const float4*)&g_xw[(size_t)s2 * HID + lane * 4];
        float4 v3 = *(const float4*)&g_xw[(size_t)s3 * HID + lane * 4];
        acc.x += (v0.x + v1.x) + (v2.x + v3.x);
        acc.y += (v0.y + v1.y) + (v2.y + v3.y);
        acc.z += (v0.z + v1.z) + (v2.z + v3.z);
        acc.w += (v0.w + v1.w) + (v2.w + v3.w);
    }
    for (; e < end; e++) {
        int s0 = __ldg(&g_csr_src[e]);
        float4 v0 = *(const float4*)&g_xw[(size_t)s0 * HID + lane * 4];
        acc.x += v0.x; acc.y += v0.y; acc.z += v0.z; acc.w += v0.w;
    }

    float nd = g_norm_dst[row];
    int k0 = lane * 4;
    float h0 = fmaxf(acc.x * nd + sb1[k0 + 0], 0.f);
    float h1 = fmaxf(acc.y * nd + sb1[k0 + 1], 0.f);
    float h2 = fmaxf(acc.z * nd + sb1[k0 + 2], 0.f);
    float h3 = fmaxf(acc.w * nd + sb1[k0 + 3], 0.f);

    float s0 = h0 * sW2[(k0 + 0) * 2] + h1 * sW2[(k0 + 1) * 2]
             + h2 * sW2[(k0 + 2) * 2] + h3 * sW2[(k0 + 3) * 2];
    float s1 = h0 * sW2[(k0 + 0) * 2 + 1] + h1 * sW2[(k0 + 1) * 2 + 1]
             + h2 * sW2[(k0 + 2) * 2 + 1] + h3 * sW2[(k0 + 3) * 2 + 1];
#pragma unroll
    for (int off = 16; off > 0; off >>= 1) {
        s0 += __shfl_down_sync(0xffffffffu, s0, off);
        s1 += __shfl_down_sync(0xffffffffu, s1, off);
    }
    if (lane == 0) {
        float ns = g_norm_src[row];
        g_zs[row * 2 + 0] = s0 * ns;
        g_zs[row * 2 + 1] = s1 * ns;
    }
}

// ---------------- fused layer2: CSR segmented sum + softmax ------------------
__global__ void agg2_fused_kernel(const float* __restrict__ b2, float* __restrict__ out) {
    int i = blockIdx.x * blockDim.x + threadIdx.x;
    if (i >= N_NODES) return;
    int start = g_row_start[i];
    int end = start + g_in_cnt[i];
    float a0 = 0.f, a1 = 0.f;
    int e = start;
    for (; e + 1 < end; e += 2) {
        int s0 = __ldg(&g_csr_src[e]);
        int s1 = __ldg(&g_csr_src[e + 1]);
        float2 v0 = *(const float2*)&g_zs[s0 * 2];
        float2 v1 = *(const float2*)&g_zs[s1 * 2];
        a0 += v0.x + v1.x;
        a1 += v0.y + v1.y;
    }
    if (e < end) {
        int s = __ldg(&g_csr_src[e]);
        float2 v = *(const float2*)&g_zs[s * 2];
        a0 += v.x;
        a1 += v.y;
    }
    float nd = g_norm_dst[i];
    float z0 = a0 * nd + __ldg(&b2[0]);
    float z1 = a1 * nd + __ldg(&b2[1]);
    float m = fmaxf(z0, z1);
    float e0 = __expf(z0 - m);
    float e1 = __expf(z1 - m);
    float inv = 1.0f / (e0 + e1);
    out[i * 2 + 0] = e0 * inv;
    out[i * 2 + 1] = e1 * inv;
}

// ---------------- host ------------------------------------------------------
extern "C" void kernel_launch(void* const* d_in, const int* in_sizes, int n_in,
                              void* d_out, int out_size) {
    const float* X  = (const float*)d_in[0];
    const float* W1 = (const float*)d_in[1];
    const float* b1 = (const float*)d_in[2];
    const float* W2 = (const float*)d_in[3];
    const float* b2 = (const float*)d_in[4];
    const void*  sp = d_in[5];
    const void*  dp = d_in[6];
    const int E = in_sizes[5];
    float* out = (float*)d_out;

    zero_kernel<<<(N_NODES + 255) / 256, 256>>>();
    detect_kernel<<<1, 1>>>(sp, E);
    convert_degree_kernel<<<(E + 255) / 256, 256>>>(sp, dp, E);
    scanA_kernel<<<NUM_SCAN_BLKS, SCAN_BLK>>>();
    scanB_kernel<<<1, 128>>>();
    scanC_kernel<<<(N_NODES + 255) / 256, 256>>>();
    scatter_kernel<<<(E + 255) / 256, 256>>>(E);
    gemm1_tc_kernel<<<(N_NODES + 127) / 128, 512>>>(X, W1);
    {
        long long threads = (long long)N_NODES * 32;
        agg1_fused_kernel<<<(unsigned)((threads + 255) / 256), 256>>>(b1, W2);
    }
    agg2_fused_kernel<<<(N_NODES + 255) / 256, 256>>>(b2, out);
}